// round 14
// baseline (speedup 1.0000x reference)
#include <cuda_runtime.h>
#include <cuda_bf16.h>

#define SEQ   4096
#define DH    2048
#define DOUT  1024
#define LN_EPS 1e-5f

#define W_SCALE    1048576.0f          // 2^20
#define W_UNSCALE  9.5367431640625e-07f // 2^-20

// ---------------------------------------------------------------------------
// Scratch (__device__ globals; allocation-free rule)
// ---------------------------------------------------------------------------
__device__ unsigned char g_W8  [(size_t)SEQ * SEQ];   // tril(W)*2^20 e4m3 [m][n]
__device__ unsigned char g_g8  [(size_t)SEQ * DH];    // LN(gate) e4m3 [n][d]
__device__ unsigned char g_g8T [(size_t)DH * SEQ];    // transpose   e4m3 [d][n]
__device__ float         g_gated[(size_t)SEQ * DH];   // gated, tf32-rounded [m][d]
__device__ float         g_pwt  [(size_t)DH * DOUT];  // proj_w, tf32-rounded [d][j]

// ---------------------------------------------------------------------------
// PTX helpers
// ---------------------------------------------------------------------------
__device__ __forceinline__ unsigned smem_u32(const void* p) {
    unsigned a;
    asm("{ .reg .u64 t; cvta.to.shared.u64 t, %1; cvt.u32.u64 %0, t; }"
        : "=r"(a) : "l"(p));
    return a;
}

__device__ __forceinline__ void ldsm_x4(unsigned* r, unsigned addr) {
    asm volatile("ldmatrix.sync.aligned.m8n8.x4.shared.b16 {%0,%1,%2,%3}, [%4];"
                 : "=r"(r[0]), "=r"(r[1]), "=r"(r[2]), "=r"(r[3]) : "r"(addr));
}

__device__ __forceinline__ void mma16832_e4m3(float* c, const unsigned* a,
                                              unsigned b0, unsigned b1) {
    asm volatile(
        "mma.sync.aligned.m16n8k32.row.col.f32.e4m3.e4m3.f32 "
        "{%0,%1,%2,%3}, {%4,%5,%6,%7}, {%8,%9}, {%0,%1,%2,%3};"
        : "+f"(c[0]), "+f"(c[1]), "+f"(c[2]), "+f"(c[3])
        : "r"(a[0]), "r"(a[1]), "r"(a[2]), "r"(a[3]), "r"(b0), "r"(b1));
}

__device__ __forceinline__ void mma1688_tf32(float* c, const unsigned* a,
                                             unsigned b0, unsigned b1) {
    asm volatile(
        "mma.sync.aligned.m16n8k8.row.col.f32.tf32.tf32.f32 "
        "{%0,%1,%2,%3}, {%4,%5,%6,%7}, {%8,%9}, {%0,%1,%2,%3};"
        : "+f"(c[0]), "+f"(c[1]), "+f"(c[2]), "+f"(c[3])
        : "r"(a[0]), "r"(a[1]), "r"(a[2]), "r"(a[3]), "r"(b0), "r"(b1));
}

__device__ __forceinline__ void cp16(unsigned dst, const void* src) {
    asm volatile("cp.async.cg.shared.global [%0], [%1], 16;"
                 :: "r"(dst), "l"(src) : "memory");
}
__device__ __forceinline__ void cp_commit() {
    asm volatile("cp.async.commit_group;" ::: "memory");
}
template <int N>
__device__ __forceinline__ void cp_wait() {
    asm volatile("cp.async.wait_group %0;" :: "n"(N) : "memory");
}

__device__ __forceinline__ unsigned to_tf32(float f) {
    unsigned u;
    asm("cvt.rna.tf32.f32 %0, %1;" : "=r"(u) : "f"(f));
    return u;
}
// pack 2 floats into 2 e4m3 bytes: lo byte = a (lower index), hi byte = b
__device__ __forceinline__ unsigned short pack_e4m3x2(float a, float b) {
    unsigned short h;
    asm("cvt.rn.satfinite.e4m3x2.f32 %0, %1, %2;" : "=h"(h) : "f"(b), "f"(a));
    return h;
}

// spatial smem (bytes): rows of 64 e4m3 padded to 80
static constexpr int SP_STR  = 80;
static constexpr int SP_BUF  = 128 * SP_STR;      // 10240 B per tile
static constexpr int SP_STAGES = 3;

// proj smem strides (fp32 elems), conflict-free for LDS.32 fragment loads
static constexpr int PJ_AS_STR = 36;    // [128][36]
static constexpr int PJ_BS_STR = 264;   // [32][264]  (BN=256 + 8 pad)
static constexpr int PJ_AS_BUF = 128 * PJ_AS_STR;
static constexpr int PJ_BS_BUF = 32 * PJ_BS_STR;
static constexpr int PJ_STAGES = 3;

// ---------------------------------------------------------------------------
// Kernel 1: LayerNorm (scale only) of gate half -> e4m3 g_g8[n][d]
// thread t handles d = t*8 .. t*8+7
// ---------------------------------------------------------------------------
__global__ __launch_bounds__(256) void ln_kernel(const float* __restrict__ x,
                                                 const float* __restrict__ ln_scale)
{
    const int row = blockIdx.x;
    const int t   = threadIdx.x;
    const float* g = x + (size_t)row * (2 * DH) + DH + t * 8;

    float v[8];
    float sum = 0.f, sumsq = 0.f;
    {
        float4 f0 = *(const float4*)(g);
        float4 f1 = *(const float4*)(g + 4);
        v[0]=f0.x; v[1]=f0.y; v[2]=f0.z; v[3]=f0.w;
        v[4]=f1.x; v[5]=f1.y; v[6]=f1.z; v[7]=f1.w;
    }
#pragma unroll
    for (int i = 0; i < 8; i++) { sum += v[i]; sumsq += v[i] * v[i]; }

    __shared__ float s1[8], s2[8];
#pragma unroll
    for (int o = 16; o > 0; o >>= 1) {
        sum   += __shfl_xor_sync(0xFFFFFFFFu, sum, o);
        sumsq += __shfl_xor_sync(0xFFFFFFFFu, sumsq, o);
    }
    const int w = t >> 5, l = t & 31;
    if (l == 0) { s1[w] = sum; s2[w] = sumsq; }
    __syncthreads();
    if (w == 0) {
        sum   = (l < 8) ? s1[l] : 0.f;
        sumsq = (l < 8) ? s2[l] : 0.f;
#pragma unroll
        for (int o = 4; o > 0; o >>= 1) {
            sum   += __shfl_xor_sync(0xFFFFFFFFu, sum, o);
            sumsq += __shfl_xor_sync(0xFFFFFFFFu, sumsq, o);
        }
        if (l == 0) { s1[0] = sum; s2[0] = sumsq; }
    }
    __syncthreads();
    const float mean = s1[0] * (1.0f / DH);
    const float var  = s2[0] * (1.0f / DH) - mean * mean;
    const float inv  = rsqrtf(var + LN_EPS);

    const float* sc = ln_scale + t * 8;
    unsigned short h[4];
#pragma unroll
    for (int i = 0; i < 4; i++) {
        float a = (v[2*i]   - mean) * inv * sc[2*i];
        float b = (v[2*i+1] - mean) * inv * sc[2*i+1];
        h[i] = pack_e4m3x2(a, b);
    }
    *(uint2*)(g_g8 + (size_t)row * DH + t * 8) =
        make_uint2(((unsigned)h[1] << 16) | h[0], ((unsigned)h[3] << 16) | h[2]);
}

// ---------------------------------------------------------------------------
// Kernel 1b: byte transpose g_g8[n][d] -> g_g8T[d][n], 64x64 tiles
// ---------------------------------------------------------------------------
__global__ __launch_bounds__(256) void transpose8_kernel()
{
    __shared__ unsigned char s[64][68];
    const int tx = threadIdx.x & 15;      // 16 cols of uchar4
    const int ty = threadIdx.x >> 4;      // 16 rows
    const int xb = blockIdx.x * 64;       // d
    const int yb = blockIdx.y * 64;       // n
#pragma unroll
    for (int i = 0; i < 4; i++) {
        const int r = ty + i * 16;
        uchar4 v = *(const uchar4*)(g_g8 + (size_t)(yb + r) * DH + xb + tx * 4);
        s[r][tx * 4 + 0] = v.x; s[r][tx * 4 + 1] = v.y;
        s[r][tx * 4 + 2] = v.z; s[r][tx * 4 + 3] = v.w;
    }
    __syncthreads();
#pragma unroll
    for (int i = 0; i < 4; i++) {
        const int r = ty + i * 16;        // d within tile
        uchar4 v;
        v.x = s[tx * 4 + 0][r]; v.y = s[tx * 4 + 1][r];
        v.z = s[tx * 4 + 2][r]; v.w = s[tx * 4 + 3][r];
        *(uchar4*)(g_g8T + (size_t)(xb + r) * SEQ + yb + tx * 4) = v;
    }
}

// ---------------------------------------------------------------------------
// Kernel 2: round proj_w to tf32 (same [d][j] layout)
// ---------------------------------------------------------------------------
__global__ __launch_bounds__(256) void pw_cvt_kernel(const float* __restrict__ pw)
{
    const size_t i = ((size_t)blockIdx.x * 256 + threadIdx.x) * 4;
    float4 v = *(const float4*)(pw + i);
    uint4 u = make_uint4(to_tf32(v.x), to_tf32(v.y), to_tf32(v.z), to_tf32(v.w));
    *(uint4*)(g_pwt + i) = u;
}

// ---------------------------------------------------------------------------
// Kernel 2b: W fp32 -> tril-masked e4m3 * 2^20  (cols < (row|127)+1 used)
// ---------------------------------------------------------------------------
__global__ __launch_bounds__(256) void w_cvt8_kernel(const float* __restrict__ W)
{
    const int row   = blockIdx.x;
    const int ncols = (row & ~127) + 128;
    const float* src = W + (size_t)row * SEQ;
    unsigned char* dst = g_W8 + (size_t)row * SEQ;

    for (int c = threadIdx.x * 8; c < ncols; c += 256 * 8) {
        float4 f0 = *(const float4*)(src + c);
        float4 f1 = *(const float4*)(src + c + 4);
        float e[8] = {f0.x, f0.y, f0.z, f0.w, f1.x, f1.y, f1.z, f1.w};
#pragma unroll
        for (int q = 0; q < 8; q++)
            e[q] = (c + q > row) ? 0.f : e[q] * W_SCALE;
        unsigned short h0 = pack_e4m3x2(e[0], e[1]);
        unsigned short h1 = pack_e4m3x2(e[2], e[3]);
        unsigned short h2 = pack_e4m3x2(e[4], e[5]);
        unsigned short h3 = pack_e4m3x2(e[6], e[7]);
        *(uint2*)(dst + c) =
            make_uint2(((unsigned)h1 << 16) | h0, ((unsigned)h3 << 16) | h2);
    }
}

// ---------------------------------------------------------------------------
// Kernel 3: spatial mixing (FP8 e4m3 m16n8k32, 3-stage cp.async).
// BM=128 BN=128 BK=64, 128 thr (2x2 warps of 64x64), 2 CTAs/SM.
// C[m][d] = sum_{n<=m} W8[m][n]*g8T[d][n];  epi: g_gated = tf32(xh*(C*2^-20 + sb))
// ---------------------------------------------------------------------------
__global__ __launch_bounds__(128, 2) void spatial_kernel(const float* __restrict__ x,
                                                         const float* __restrict__ sb)
{
    extern __shared__ unsigned char sm8[];
    unsigned char* As = sm8;                          // [S][128][80] bytes (m x k)
    unsigned char* Bs = sm8 + SP_STAGES * SP_BUF;     // [S][128][80] bytes (d x k)

    const int tid  = threadIdx.x;
    const int lane = tid & 31;
    const int wid  = tid >> 5;
    const int ntile = blockIdx.x & 15;
    const int mtile = 31 - (blockIdx.x >> 4);   // heavy tiles first
    const int m0 = mtile * 128;
    const int n0 = ntile * 128;                 // d-tile
    const int wm = wid & 1;      // 2 warps along M (64 rows)
    const int wn = wid >> 1;     // 2 warps along N (64 d-cols)

    float acc[4][8][4];
#pragma unroll
    for (int i = 0; i < 4; i++)
#pragma unroll
        for (int j = 0; j < 8; j++)
#pragma unroll
            for (int q = 0; q < 4; q++) acc[i][j][q] = 0.f;

    // A: 128 rows x 64 B; 128 thr -> one row each (4 cp16)
    auto cpA = [&](int buf, int k0) {
        const unsigned char* src = g_W8 + (size_t)(m0 + tid) * SEQ + k0;
        unsigned dst = smem_u32(As + buf * SP_BUF + tid * SP_STR);
        cp16(dst,      src);
        cp16(dst + 16, src + 16);
        cp16(dst + 32, src + 32);
        cp16(dst + 48, src + 48);
    };
    // B: 128 d-rows x 64 B from g_g8T
    auto cpB = [&](int buf, int k0) {
        const unsigned char* src = g_g8T + (size_t)(n0 + tid) * SEQ + k0;
        unsigned dst = smem_u32(Bs + buf * SP_BUF + tid * SP_STR);
        cp16(dst,      src);
        cp16(dst + 16, src + 16);
        cp16(dst + 32, src + 32);
        cp16(dst + 48, src + 48);
    };
    auto compute = [&](int buf) {
        const unsigned char* A0 = As + buf * SP_BUF;
        const unsigned char* B0 = Bs + buf * SP_BUF;
#pragma unroll
        for (int ks = 0; ks < 2; ks++) {     // two k32 steps per 64-K buf
            unsigned a[4][4], b[4][4];
#pragma unroll
            for (int mb = 0; mb < 4; mb++)
                ldsm_x4(a[mb], smem_u32(A0 + (wm * 64 + mb * 16 + (lane & 15)) * SP_STR
                                           + ks * 32 + (lane >> 4) * 16));
#pragma unroll
            for (int pb = 0; pb < 4; pb++)   // 16 d-rows per x4 -> 2 n8 frags
                ldsm_x4(b[pb], smem_u32(B0 + (wn * 64 + pb * 16 + (lane & 15)) * SP_STR
                                           + ks * 32 + (lane >> 4) * 16));
#pragma unroll
            for (int mb = 0; mb < 4; mb++)
#pragma unroll
                for (int pb = 0; pb < 4; pb++) {
                    // frag (pb, n8=0): regs {0,2}; (pb, n8=1): regs {1,3}
                    mma16832_e4m3(acc[mb][2 * pb + 0], a[mb], b[pb][0], b[pb][2]);
                    mma16832_e4m3(acc[mb][2 * pb + 1], a[mb], b[pb][1], b[pb][3]);
                }
        }
    };

    const int nch = 2 * mtile + 2;       // kend = m0+128, BK=64

#pragma unroll
    for (int s = 0; s < SP_STAGES - 1; s++) {
        if (s < nch) { cpA(s, s * 64); cpB(s, s * 64); }
        cp_commit();
    }
    for (int i = 0; i < nch; i++) {
        cp_wait<SP_STAGES - 2>();
        __syncthreads();
        const int nx = i + SP_STAGES - 1;
        if (nx < nch) { cpA(nx % SP_STAGES, nx * 64); cpB(nx % SP_STAGES, nx * 64); }
        cp_commit();
        compute(i % SP_STAGES);
    }

    // epilogue: g_gated = tf32( xh * (acc*2^-20 + sb[m]) )
#pragma unroll
    for (int mb = 0; mb < 4; mb++) {
        const int gmb = m0 + wm * 64 + mb * 16 + (lane >> 2);
#pragma unroll
        for (int nb = 0; nb < 8; nb++) {
            const int gc = n0 + wn * 64 + nb * 8 + (lane & 3) * 2;
#pragma unroll
            for (int half = 0; half < 2; half++) {
                const int gm = gmb + half * 8;
                const float bias = sb[gm];
                const float2 xv = *(const float2*)(x + (size_t)gm * SEQ + gc);
                float v0 = xv.x * (acc[mb][nb][half * 2 + 0] * W_UNSCALE + bias);
                float v1 = xv.y * (acc[mb][nb][half * 2 + 1] * W_UNSCALE + bias);
                *(uint2*)(g_gated + (size_t)gm * DH + gc) =
                    make_uint2(to_tf32(v0), to_tf32(v1));
            }
        }
    }
}

// ---------------------------------------------------------------------------
// Kernel 4: projection (tf32 m16n8k8, 3-stage cp.async).
// BM=128 BN=256 BK=32, 256 thr, warp tile 64x64 (2x4 warps).
// ---------------------------------------------------------------------------
__global__ __launch_bounds__(256) void proj_kernel(const float* __restrict__ pb,
                                                   float* __restrict__ out)
{
    extern __shared__ float smf[];
    float* Af = smf;                           // [S][128][36]
    float* Bf = smf + PJ_STAGES * PJ_AS_BUF;   // [S][32][264]

    const int tid  = threadIdx.x;
    const int lane = tid & 31;
    const int wid  = tid >> 5;
    const int ntile = blockIdx.x & 3;
    const int mtile = blockIdx.x >> 2;
    const int m0 = mtile * 128;
    const int n0 = ntile * 256;
    const int wm = wid & 1;      // 2 warps M (64 rows)
    const int wn = wid >> 1;     // 4 warps N (64 cols)
    const int g = lane >> 2;     // groupID 0..7
    const int t = lane & 3;      // thread-in-group

    float acc[4][8][4];
#pragma unroll
    for (int i = 0; i < 4; i++)
#pragma unroll
        for (int j = 0; j < 8; j++)
#pragma unroll
            for (int q = 0; q < 4; q++) acc[i][j][q] = 0.f;

    auto cpStage = [&](int buf, int k0) {
#pragma unroll
        for (int it = 0; it < 4; it++) {       // A tile [128][32] fp32
            const int idx = tid + it * 256;
            const int r = idx >> 3;
            const int c = (idx & 7) * 4;
            cp16(smem_u32(Af + buf * PJ_AS_BUF + r * PJ_AS_STR + c),
                 g_gated + (size_t)(m0 + r) * DH + k0 + c);
        }
#pragma unroll
        for (int it = 0; it < 8; it++) {       // B tile [32][256] fp32
            const int idx = tid + it * 256;
            const int r = idx >> 6;
            const int c = (idx & 63) * 4;
            cp16(smem_u32(Bf + buf * PJ_BS_BUF + r * PJ_BS_STR + c),
                 g_pwt + (size_t)(k0 + r) * DOUT + n0 + c);
        }
    };
    auto compute = [&](int buf) {
        const float* A0 = Af + buf * PJ_AS_BUF;
        const float* B0 = Bf + buf * PJ_BS_BUF;
#pragma unroll
        for (int ks = 0; ks < 4; ks++) {
            unsigned a[4][4], b[8][2];
#pragma unroll
            for (int mb = 0; mb < 4; mb++) {
                const float* Ap = A0 + (wm * 64 + mb * 16) * PJ_AS_STR + ks * 8;
                a[mb][0] = __float_as_uint(Ap[(g    ) * PJ_AS_STR + t    ]);
                a[mb][1] = __float_as_uint(Ap[(g + 8) * PJ_AS_STR + t    ]);
                a[mb][2] = __float_as_uint(Ap[(g    ) * PJ_AS_STR + t + 4]);
                a[mb][3] = __float_as_uint(Ap[(g + 8) * PJ_AS_STR + t + 4]);
            }
#pragma unroll
            for (int nb = 0; nb < 8; nb++) {
                const float* Bp = B0 + ks * 8 * PJ_BS_STR + wn * 64 + nb * 8 + g;
                b[nb][0] = __float_as_uint(Bp[ t      * PJ_BS_STR]);
                b[nb][1] = __float_as_uint(Bp[(t + 4) * PJ_BS_STR]);
            }
#pragma unroll
            for (int mb = 0; mb < 4; mb++)
#pragma unroll
                for (int nb = 0; nb < 8; nb++)
                    mma1688_tf32(acc[mb][nb], a[mb], b[nb][0], b[nb][1]);
        }
    };

    const int nch = DH / 32;   // 64

#pragma unroll
    for (int s = 0; s < PJ_STAGES - 1; s++) {
        cpStage(s, s * 32);
        cp_commit();
    }
    for (int i = 0; i < nch; i++) {
        cp_wait<PJ_STAGES - 2>();
        __syncthreads();
        const int nx = i + PJ_STAGES - 1;
        if (nx < nch) cpStage(nx % PJ_STAGES, nx * 32);
        cp_commit();
        compute(i % PJ_STAGES);
    }

    // epilogue: + pb
#pragma unroll
    for (int mb = 0; mb < 4; mb++) {
        const int gmb = m0 + wm * 64 + mb * 16 + g;
#pragma unroll
        for (int nb = 0; nb < 8; nb++) {
            const int gc = n0 + wn * 64 + nb * 8 + t * 2;
            const float2 bias = *(const float2*)(pb + gc);
#pragma unroll
            for (int half = 0; half < 2; half++) {
                const int gm = gmb + half * 8;
                float2 o;
                o.x = acc[mb][nb][half * 2 + 0] + bias.x;
                o.y = acc[mb][nb][half * 2 + 1] + bias.y;
                *(float2*)(out + (size_t)gm * DOUT + gc) = o;
            }
        }
    }
}

// ---------------------------------------------------------------------------
extern "C" void kernel_launch(void* const* d_in, const int* in_sizes, int n_in,
                              void* d_out, int out_size)
{
    const float* x        = (const float*)d_in[0];  // (4096, 4096)
    const float* ln_scale = (const float*)d_in[1];  // (2048,)
    const float* W        = (const float*)d_in[2];  // (4096, 4096)
    const float* sb       = (const float*)d_in[3];  // (4096, 1)
    const float* pw       = (const float*)d_in[4];  // (2048, 1024)
    const float* pb       = (const float*)d_in[5];  // (1024,)
    float* out            = (float*)d_out;          // (4096, 1024)

    const int SP_SMEM = SP_STAGES * 2 * SP_BUF;                   // 61440 B
    const int PJ_SMEM = PJ_STAGES * (PJ_AS_BUF + PJ_BS_BUF) * 4;  // 156672 B
    cudaFuncSetAttribute(spatial_kernel,
                         cudaFuncAttributeMaxDynamicSharedMemorySize, SP_SMEM);
    cudaFuncSetAttribute(proj_kernel,
                         cudaFuncAttributeMaxDynamicSharedMemorySize, PJ_SMEM);

    ln_kernel<<<SEQ, 256>>>(x, ln_scale);
    transpose8_kernel<<<dim3(DH / 64, SEQ / 64), 256>>>();
    w_cvt8_kernel<<<SEQ, 256>>>(W);
    pw_cvt_kernel<<<(DH * DOUT) / (256 * 4), 256>>>(pw);
    spatial_kernel<<<512, 128, SP_SMEM>>>(x, sb);
    proj_kernel<<<128, 256, PJ_SMEM>>>(pb, out);
}